// round 13
// baseline (speedup 1.0000x reference)
#include <cuda_runtime.h>
#include <cuda_fp16.h>
#include <cstdint>

#define D 4096
#define E 64
#define BM 64            // tokens per CTA
#define BK 64            // k per chunk
#define NT 256
#define NCHUNK (D / BK)  // 64
#define AST 72           // B smem row stride in fp16 elems (144 B)
#define MAXBLK 256
#define MAXT 16384

// ---- device scratch ----
__device__ __half g_whT[E * D];          // W^T fp16  [n][k]
__device__ float g_Ppart[MAXBLK * E];
__device__ float g_Mpart[MAXBLK * E];
__device__ int   g_topidx[MAXT];
__device__ float g_topprob[MAXT];
__device__ float g_P[E];
__device__ float g_M[E];

__device__ __forceinline__ uint32_t smem_u32(const void* p) {
    uint32_t a;
    asm("{ .reg .u64 t; cvta.to.shared.u64 t, %1; cvt.u32.u64 %0, t; }"
        : "=r"(a) : "l"(p));
    return a;
}

__device__ __forceinline__ void ldsm_x4(uint32_t& r0, uint32_t& r1,
                                        uint32_t& r2, uint32_t& r3, uint32_t addr) {
    asm volatile("ldmatrix.sync.aligned.m8n8.x4.shared.b16 {%0,%1,%2,%3}, [%4];"
                 : "=r"(r0), "=r"(r1), "=r"(r2), "=r"(r3) : "r"(addr));
}

__device__ __forceinline__ void mma_f16(float* c, const uint32_t* a,
                                        uint32_t b0, uint32_t b1) {
    asm volatile(
        "mma.sync.aligned.m16n8k16.row.col.f32.f16.f16.f32 "
        "{%0,%1,%2,%3}, {%4,%5,%6,%7}, {%8,%9}, {%0,%1,%2,%3};"
        : "+f"(c[0]), "+f"(c[1]), "+f"(c[2]), "+f"(c[3])
        : "r"(a[0]), "r"(a[1]), "r"(a[2]), "r"(a[3]), "r"(b0), "r"(b1));
}

__device__ __forceinline__ uint32_t cvt2h(float a, float b) {
    __half2 h = __floats2half2_rn(a, b);
    return *(uint32_t*)&h;
}

// ---- W transpose to fp16, coalesced via smem tile (grid = D/16) ----
__global__ void wsplit_kernel(const float* __restrict__ W) {
    __shared__ float tile[16][65];
    const int k0 = blockIdx.x * 16;
    const int tid = threadIdx.x;          // 256
#pragma unroll
    for (int j = 0; j < 4; j++) {
        int idx = tid + j * 256;
        int k = idx >> 6, n = idx & 63;
        tile[k][n] = W[(size_t)(k0 + k) * E + n];
    }
    __syncthreads();
#pragma unroll
    for (int j = 0; j < 4; j++) {
        int idx = tid + j * 256;
        int n = idx >> 4, k = idx & 15;
        g_whT[(size_t)n * D + k0 + k] = __float2half_rn(tile[k][n]);
    }
}

// ---- fused router: direct-register A, smem B, k-split m32n64 warps ----
__global__ __launch_bounds__(NT, 2) void router_kernel(
    const float* __restrict__ x, const float* __restrict__ bias,
    float* __restrict__ out, int T)
{
    __shared__ union {
        __align__(16) unsigned short bh[2][E * AST];   // 2 x 9216 B
        float lsm[BM][E + 1];                          // 16640 B (overlay)
    } smA;
    __shared__ float bs[E];
    __shared__ float red_m[BM], red_s[BM], red_p[BM];
    __shared__ int   red_i[BM];
    __shared__ float Pp[4][E];

    const int tid = threadIdx.x;
    const int wid = tid >> 5;
    const int lid = tid & 31;
    const size_t t0 = (size_t)blockIdx.x * BM;

    if (tid < E) bs[tid] = bias[tid];

    // warp mapping: mg = m32 group, kg = k16 group within BK=64
    const int mg = wid & 1;
    const int kg = wid >> 1;

    // ---- A direct-load geometry (per lane) ----
    // fragment lane l: rows base + l/4 (+8,+16,+24); k = kg*16 + (l&3)*2 (+8)
    const float* xa = x + (t0 + mg * 32 + (lid >> 2)) * D + kg * 16 + (lid & 3) * 2;

    // ---- B tile fill geometry (per thread): row n = tid>>2, 32B of k ----
    const int brow = tid >> 2;
    const int bq   = tid & 3;
    const unsigned char* whg = (const unsigned char*)g_whT + (size_t)brow * D * 2 + bq * 32;
    const uint32_t st_off = (uint32_t)(brow * 144 + bq * 32);

    const uint32_t bhb[2] = { smem_u32(&smA.bh[0][0]), smem_u32(&smA.bh[1][0]) };

    // per-lane ldmatrix offsets: 4 n-groups x (k16 of this warp's kg)
    const int lg = lid >> 3;
    const int lr = lid & 7;
    uint32_t b_off[4];
#pragma unroll
    for (int g = 0; g < 4; g++)
        b_off[g] = (uint32_t)((g * 16 + (lg >> 1) * 8 + lr) * 144 + (lg & 1) * 16
                              + kg * 32);

    float acc[2][8][4];
#pragma unroll
    for (int mf = 0; mf < 2; mf++)
#pragma unroll
        for (int nf = 0; nf < 8; nf++)
#pragma unroll
            for (int q = 0; q < 4; q++) acc[mf][nf][q] = 0.f;

    uint4 bv[2];
#define LOAD_B(chunk) do {                                                      \
        const int _k0 = (chunk) * BK;                                           \
        bv[0] = *(const uint4*)(whg + _k0 * 2);                                 \
        bv[1] = *(const uint4*)(whg + _k0 * 2 + 16);                            \
    } while (0)
#define STORE_B(bufi) do {                                                      \
        *(uint4*)((unsigned char*)&smA.bh[bufi][0] + st_off)      = bv[0];      \
        *(uint4*)((unsigned char*)&smA.bh[bufi][0] + st_off + 16) = bv[1];      \
    } while (0)

    // prologue: B chunk0 -> buf0; B chunk1 staged in regs
    LOAD_B(0); STORE_B(0);
    LOAD_B(1);
    __syncthreads();

#pragma unroll 1
    for (int i = 0; i < NCHUNK; i++) {
        const int buf = i & 1;
        const int k0  = i * BK;

        // A: 8 x LDG.64 direct from gmem (each 32B sector fully used per quad)
        float2 av[8];
#pragma unroll
        for (int r4 = 0; r4 < 4; r4++)
#pragma unroll
            for (int k2 = 0; k2 < 2; k2++)
                av[r4 * 2 + k2] = *(const float2*)(xa + k0 + (size_t)(r4 * 8) * D + k2 * 8);

        // B fragments from smem
        uint32_t b[16];
#pragma unroll
        for (int g = 0; g < 4; g++)
            ldsm_x4(b[4 * g], b[4 * g + 1], b[4 * g + 2], b[4 * g + 3],
                    bhb[buf] + b_off[g]);

        // A fragments (register convert, no smem)
        uint32_t a[2][4];
        a[0][0] = cvt2h(av[0].x, av[0].y);
        a[0][1] = cvt2h(av[2].x, av[2].y);
        a[0][2] = cvt2h(av[1].x, av[1].y);
        a[0][3] = cvt2h(av[3].x, av[3].y);
        a[1][0] = cvt2h(av[4].x, av[4].y);
        a[1][1] = cvt2h(av[6].x, av[6].y);
        a[1][2] = cvt2h(av[5].x, av[5].y);
        a[1][3] = cvt2h(av[7].x, av[7].y);

        // 16 MMAs: m32 x n64 x k16
#pragma unroll
        for (int mf = 0; mf < 2; mf++)
#pragma unroll
            for (int g = 0; g < 4; g++) {
                mma_f16(acc[mf][2 * g],     a[mf], b[4 * g],     b[4 * g + 1]);
                mma_f16(acc[mf][2 * g + 1], a[mf], b[4 * g + 2], b[4 * g + 3]);
            }

        // rotate B staging
        if (i + 1 < NCHUNK) STORE_B(buf ^ 1);
        if (i + 2 < NCHUNK) LOAD_B(i + 2);
        __syncthreads();
    }
#undef LOAD_B
#undef STORE_B

    // ---- k-split reduction into logits (4 deterministic phases) ----
    {
        const int mr = mg * 32 + (lid >> 2);
        const int nc = (lid & 3) * 2;
#pragma unroll 1
        for (int p = 0; p < 4; p++) {
            if (kg == p) {
#pragma unroll
                for (int mf = 0; mf < 2; mf++)
#pragma unroll
                    for (int nf = 0; nf < 8; nf++) {
                        const int r = mr + mf * 16;
                        const int c = nc + nf * 8;
                        if (p == 0) {
                            smA.lsm[r][c]         = acc[mf][nf][0];
                            smA.lsm[r][c + 1]     = acc[mf][nf][1];
                            smA.lsm[r + 8][c]     = acc[mf][nf][2];
                            smA.lsm[r + 8][c + 1] = acc[mf][nf][3];
                        } else {
                            smA.lsm[r][c]         += acc[mf][nf][0];
                            smA.lsm[r][c + 1]     += acc[mf][nf][1];
                            smA.lsm[r + 8][c]     += acc[mf][nf][2];
                            smA.lsm[r + 8][c + 1] += acc[mf][nf][3];
                        }
                    }
            }
            __syncthreads();
        }
    }

    // phase 1: per-token max / first-index argmax / 1/sum(exp)
    if (tid < BM) {
        int t = tid;
        float m = -1e30f; int bi = 0;
#pragma unroll 8
        for (int e = 0; e < E; e++) {
            float v = smA.lsm[t][e] + bs[e];
            if (v > m) { m = v; bi = e; }     // strict '>' => first occurrence
        }
        float ssum = 0.f;
#pragma unroll 8
        for (int e = 0; e < E; e++)
            ssum += __expf(smA.lsm[t][e] + bs[e] - m);
        float rs = 1.0f / ssum;               // top-1 prob
        red_m[t] = m; red_s[t] = rs; red_i[t] = bi; red_p[t] = rs;
        g_topidx[t0 + t]  = bi;
        g_topprob[t0 + t] = rs;
    }
    __syncthreads();

    // phase 2: write softmax probs; per-expert P partials
    {
        int e  = tid & 63;
        int th = tid >> 6;                     // 0..3, 16 tokens each
        float Psum = 0.f;
        float be = bs[e];
        for (int t = th * 16; t < th * 16 + 16; t++) {
            float pv = __expf(smA.lsm[t][e] + be - red_m[t]) * red_s[t];
            out[(t0 + t) * E + e] = pv;
            Psum += pv;
        }
        Pp[th][e] = Psum;
    }
    __syncthreads();

    if (tid < E) {
        int e = tid;
        float Msum = 0.f;
        for (int t = 0; t < BM; t++)
            if (red_i[t] == e) Msum += red_p[t];
        g_Ppart[blockIdx.x * E + e] = Pp[0][e] + Pp[1][e] + Pp[2][e] + Pp[3][e];
        g_Mpart[blockIdx.x * E + e] = Msum;
    }
}

// ---- one-block reduce: partials -> g_P/g_M + aux loss ----
__global__ void reduce_kernel(float* __restrict__ out, int T, int nblk, int out_size)
{
    __shared__ float s[E];
    int e = threadIdx.x;   // 64 threads
    float P = 0.f, M = 0.f;
    for (int b = 0; b < nblk; b++) {
        P += g_Ppart[b * E + e];
        M += g_Mpart[b * E + e];
    }
    g_P[e] = P; g_M[e] = M;
    float Tf = (float)T;
    s[e] = (M / Tf) * (P / Tf);
    __syncthreads();
    if (e == 0) {
        float acc = 0.f;
        for (int i = 0; i < E; i++) acc += s[i];
        if (out_size > T * E) out[(size_t)T * E] = 0.01f * 64.0f * acc;
    }
}

// ---- light capacity fixup (fast path: two LDGs per token) ----
__global__ void fixup_kernel(float* __restrict__ out, int T, float cap)
{
    int t = blockIdx.x * blockDim.x + threadIdx.x;
    if (t >= T) return;
    int e = g_topidx[t];
    float M = g_M[e];
    if (M <= cap) return;           // expert under capacity -> assigned
    float p = g_topprob[t];
    float prefix = 0.f;
    for (int t2 = 0; t2 < T; t2++) {
        if (g_topidx[t2] == e) {
            float p2 = g_topprob[t2];
            if (p2 > p || (p2 == p && t2 <= t)) prefix += p2;
        }
    }
    if (prefix > cap) {
#pragma unroll
        for (int j = 0; j < E; j++) out[(size_t)t * E + j] = 0.f;
    }
}

extern "C" void kernel_launch(void* const* d_in, const int* in_sizes, int n_in,
                              void* d_out, int out_size)
{
    const float* x    = (const float*)d_in[0];
    const float* W    = (const float*)d_in[1];
    const float* bias = (const float*)d_in[2];
    float* out = (float*)d_out;

    int T = in_sizes[0] / D;                          // 16384
    int nblk = T / BM;                                // 256
    float cap = (float)(int)((double)T / (double)E);  // 256

    wsplit_kernel<<<D / 16, 256>>>(W);
    router_kernel<<<nblk, NT>>>(x, bias, out, T);
    reduce_kernel<<<1, E>>>(out, T, nblk, out_size);
    fixup_kernel<<<(T + 255) / 256, 256>>>(out, T, cap);
}

// round 14
// speedup vs baseline: 1.0900x; 1.0900x over previous
#include <cuda_runtime.h>
#include <cuda_fp16.h>
#include <cstdint>

#define D 4096
#define E 64
#define BM 64            // tokens per CTA
#define BK 64            // k per chunk
#define NT 256
#define NCHUNK (D / BK)  // 64
#define AST 72           // smem row stride in fp16 elems (144 B)
#define MAXBLK 256
#define MAXT 16384

// ---- device scratch ----
__device__ __half g_whT[E * D];          // W^T fp16  [n][k]
__device__ float g_Ppart[MAXBLK * E];
__device__ float g_Mpart[MAXBLK * E];
__device__ int   g_topidx[MAXT];
__device__ float g_topprob[MAXT];

__device__ __forceinline__ uint32_t smem_u32(const void* p) {
    uint32_t a;
    asm("{ .reg .u64 t; cvta.to.shared.u64 t, %1; cvt.u32.u64 %0, t; }"
        : "=r"(a) : "l"(p));
    return a;
}

__device__ __forceinline__ void ldsm_x4(uint32_t& r0, uint32_t& r1,
                                        uint32_t& r2, uint32_t& r3, uint32_t addr) {
    asm volatile("ldmatrix.sync.aligned.m8n8.x4.shared.b16 {%0,%1,%2,%3}, [%4];"
                 : "=r"(r0), "=r"(r1), "=r"(r2), "=r"(r3) : "r"(addr));
}

__device__ __forceinline__ void mma_f16(float* c, const uint32_t* a,
                                        uint32_t b0, uint32_t b1) {
    asm volatile(
        "mma.sync.aligned.m16n8k16.row.col.f32.f16.f16.f32 "
        "{%0,%1,%2,%3}, {%4,%5,%6,%7}, {%8,%9}, {%0,%1,%2,%3};"
        : "+f"(c[0]), "+f"(c[1]), "+f"(c[2]), "+f"(c[3])
        : "r"(a[0]), "r"(a[1]), "r"(a[2]), "r"(a[3]), "r"(b0), "r"(b1));
}

__device__ __forceinline__ uint32_t cvt2h(float a, float b) {
    __half2 h = __floats2half2_rn(a, b);
    return *(uint32_t*)&h;
}

// ---- W transpose to fp16, coalesced via smem tile (grid = D/16) ----
__global__ void wsplit_kernel(const float* __restrict__ W) {
    __shared__ float tile[16][65];
    const int k0 = blockIdx.x * 16;
    const int tid = threadIdx.x;          // 256
#pragma unroll
    for (int j = 0; j < 4; j++) {
        int idx = tid + j * 256;
        int k = idx >> 6, n = idx & 63;
        tile[k][n] = W[(size_t)(k0 + k) * E + n];
    }
    __syncthreads();
#pragma unroll
    for (int j = 0; j < 4; j++) {
        int idx = tid + j * 256;
        int n = idx >> 4, k = idx & 15;
        g_whT[(size_t)n * D + k0 + k] = __float2half_rn(tile[k][n]);
    }
}

// ---- fused router: HMMA fp16 GEMM (k-split m32n32 warps) + softmax + top1 ----
__global__ __launch_bounds__(NT, 2) void router_kernel(
    const float* __restrict__ x, const float* __restrict__ bias,
    float* __restrict__ out, int T)
{
    __shared__ union {
        struct {
            __align__(16) unsigned short ah[2][BM * AST];   // 2 x 9216 B
            __align__(16) unsigned short bh[2][E * AST];    // 2 x 9216 B
        } t;                                     // 36864 B
        float lsm[BM][E + 1];                    // 16640 B (overlay)
    } smA;
    __shared__ float bs[E];
    __shared__ float red_m[BM], red_s[BM], red_p[BM];
    __shared__ int   red_i[BM];
    __shared__ float Pp[4][E];

    const int tid = threadIdx.x;
    const int wid = tid >> 5;
    const int lid = tid & 31;
    const size_t t0 = (size_t)blockIdx.x * BM;

    if (tid < E) bs[tid] = bias[tid];

    // load geometry: row = tid>>2 (0..63), kq = tid&3 (16 k-values each)
    const int row = tid >> 2;
    const int kq  = tid & 3;
    const float* xg = x + (t0 + row) * D + kq * 16;
    const unsigned char* whg = (const unsigned char*)g_whT + (size_t)row * D * 2 + kq * 32;

    // warp mapping: tile = wid&3 (m32 x n32), k-group = wid>>2
    const int tw     = wid & 3;
    const int kg     = wid >> 2;
    const int m_base = (tw & 1) * 32;
    const int n_base = (tw >> 1) * 32;
    const uint32_t kbase = (uint32_t)(kg * 64);   // byte offset of this warp's k16 pair

    const uint32_t ahb[2] = { smem_u32(&smA.t.ah[0][0]), smem_u32(&smA.t.ah[1][0]) };
    const uint32_t bhb[2] = { smem_u32(&smA.t.bh[0][0]), smem_u32(&smA.t.bh[1][0]) };

    // per-lane ldmatrix row offsets (row stride 144 B)
    const int lg  = lid >> 3;
    const int lr  = lid & 7;
    const uint32_t a_off  = (uint32_t)((m_base + (lg & 1) * 8 + lr) * 144 + (lg >> 1) * 16);
    const uint32_t a_off2 = a_off + 16 * 144;     // rows m_base+16..31
    const uint32_t b_off0 = (uint32_t)((n_base + (lg >> 1) * 8 + lr) * 144 + (lg & 1) * 16);
    const uint32_t b_off1 = b_off0 + 16 * 144;    // n_base+16..31

    float acc[2][4][4];
#pragma unroll
    for (int h = 0; h < 2; h++)
#pragma unroll
        for (int f = 0; f < 4; f++)
#pragma unroll
            for (int q = 0; q < 4; q++) acc[h][f][q] = 0.f;

    const uint32_t st_off = (uint32_t)(row * 144 + kq * 32);   // per-thread STS base

    float4 xva[4], xvb[4]; uint4 bva[2], bvb[2];

#define LOAD_REGS(xv, bv, chunk) do {                                           \
        const int _k0 = (chunk) * BK;                                           \
        _Pragma("unroll")                                                       \
        for (int _j = 0; _j < 4; _j++) xv[_j] = *(const float4*)(xg + _k0 + _j * 4); \
        _Pragma("unroll")                                                       \
        for (int _j = 0; _j < 2; _j++) bv[_j] = *(const uint4*)(whg + _k0 * 2 + _j * 16); \
    } while (0)

#define STORE_TILE(bufi, xv, bv) do {                                           \
        uint4 _q0 = make_uint4(cvt2h(xv[0].x, xv[0].y), cvt2h(xv[0].z, xv[0].w), \
                               cvt2h(xv[1].x, xv[1].y), cvt2h(xv[1].z, xv[1].w)); \
        uint4 _q1 = make_uint4(cvt2h(xv[2].x, xv[2].y), cvt2h(xv[2].z, xv[2].w), \
                               cvt2h(xv[3].x, xv[3].y), cvt2h(xv[3].z, xv[3].w)); \
        *(uint4*)((unsigned char*)&smA.t.ah[bufi][0] + st_off)      = _q0;      \
        *(uint4*)((unsigned char*)&smA.t.ah[bufi][0] + st_off + 16) = _q1;      \
        *(uint4*)((unsigned char*)&smA.t.bh[bufi][0] + st_off)      = bv[0];    \
        *(uint4*)((unsigned char*)&smA.t.bh[bufi][0] + st_off + 16) = bv[1];    \
    } while (0)

#define COMPUTE(bufi) do {                                                      \
        _Pragma("unroll")                                                       \
        for (int _s = 0; _s < 2; _s++) {                                        \
            const uint32_t _ko = kbase + (uint32_t)(_s * 32);                   \
            uint32_t _a1[4], _a2[4], _b8[8];                                    \
            ldsm_x4(_a1[0], _a1[1], _a1[2], _a1[3], ahb[bufi] + a_off  + _ko);  \
            ldsm_x4(_a2[0], _a2[1], _a2[2], _a2[3], ahb[bufi] + a_off2 + _ko);  \
            ldsm_x4(_b8[0], _b8[1], _b8[2], _b8[3], bhb[bufi] + b_off0 + _ko);  \
            ldsm_x4(_b8[4], _b8[5], _b8[6], _b8[7], bhb[bufi] + b_off1 + _ko);  \
            _Pragma("unroll")                                                   \
            for (int _f = 0; _f < 4; _f++) {                                    \
                mma_f16(acc[0][_f], _a1, _b8[2 * _f], _b8[2 * _f + 1]);         \
                mma_f16(acc[1][_f], _a2, _b8[2 * _f], _b8[2 * _f + 1]);         \
            }                                                                   \
        }                                                                       \
    } while (0)

    // ---- prologue: chunk0 -> buf0; chunk1 -> regs a ----
    LOAD_REGS(xva, bva, 0);
    STORE_TILE(0, xva, bva);
    LOAD_REGS(xva, bva, 1);
    __syncthreads();

    // ---- mainloop, unrolled by 2 (depth-2 prefetch) ----
#pragma unroll 1
    for (int i = 0; i < NCHUNK; i += 2) {
        if (i + 2 < NCHUNK) LOAD_REGS(xvb, bvb, i + 2);
        COMPUTE(0);
        STORE_TILE(1, xva, bva);
        __syncthreads();
        if (i + 3 < NCHUNK) LOAD_REGS(xva, bva, i + 3);
        COMPUTE(1);
        if (i + 2 < NCHUNK) STORE_TILE(0, xvb, bvb);
        __syncthreads();
    }

    // ---- spill logits: kg=0 writes, kg=1 accumulates (k-split reduction) ----
    {
        const int mr = m_base + (lid >> 2);
        const int nc = n_base + (lid & 3) * 2;
        if (kg == 0) {
#pragma unroll
            for (int f = 0; f < 4; f++) {
                smA.lsm[mr][nc + f * 8]          = acc[0][f][0];
                smA.lsm[mr][nc + f * 8 + 1]      = acc[0][f][1];
                smA.lsm[mr + 8][nc + f * 8]      = acc[0][f][2];
                smA.lsm[mr + 8][nc + f * 8 + 1]  = acc[0][f][3];
                smA.lsm[mr + 16][nc + f * 8]     = acc[1][f][0];
                smA.lsm[mr + 16][nc + f * 8 + 1] = acc[1][f][1];
                smA.lsm[mr + 24][nc + f * 8]     = acc[1][f][2];
                smA.lsm[mr + 24][nc + f * 8 + 1] = acc[1][f][3];
            }
        }
        __syncthreads();
        if (kg == 1) {
#pragma unroll
            for (int f = 0; f < 4; f++) {
                smA.lsm[mr][nc + f * 8]          += acc[0][f][0];
                smA.lsm[mr][nc + f * 8 + 1]      += acc[0][f][1];
                smA.lsm[mr + 8][nc + f * 8]      += acc[0][f][2];
                smA.lsm[mr + 8][nc + f * 8 + 1]  += acc[0][f][3];
                smA.lsm[mr + 16][nc + f * 8]     += acc[1][f][0];
                smA.lsm[mr + 16][nc + f * 8 + 1] += acc[1][f][1];
                smA.lsm[mr + 24][nc + f * 8]     += acc[1][f][2];
                smA.lsm[mr + 24][nc + f * 8 + 1] += acc[1][f][3];
            }
        }
    }
    __syncthreads();

    // phase 1: per-token max / first-index argmax / 1/sum(exp)
    if (tid < BM) {
        int t = tid;
        float m = -1e30f; int bi = 0;
#pragma unroll 8
        for (int e = 0; e < E; e++) {
            float v = smA.lsm[t][e] + bs[e];
            if (v > m) { m = v; bi = e; }     // strict '>' => first occurrence
        }
        float ssum = 0.f;
#pragma unroll 8
        for (int e = 0; e < E; e++)
            ssum += __expf(smA.lsm[t][e] + bs[e] - m);
        float rs = 1.0f / ssum;               // top-1 prob
        red_m[t] = m; red_s[t] = rs; red_i[t] = bi; red_p[t] = rs;
        g_topidx[t0 + t]  = bi;
        g_topprob[t0 + t] = rs;
    }
    __syncthreads();

    // phase 2: write softmax probs; per-expert P partials
    {
        int e  = tid & 63;
        int th = tid >> 6;                     // 0..3, 16 tokens each
        float Psum = 0.f;
        float be = bs[e];
        for (int t = th * 16; t < th * 16 + 16; t++) {
            float pv = __expf(smA.lsm[t][e] + be - red_m[t]) * red_s[t];
            out[(t0 + t) * E + e] = pv;
            Psum += pv;
        }
        Pp[th][e] = Psum;
    }
    __syncthreads();

    if (tid < E) {
        int e = tid;
        float Msum = 0.f;
        for (int t = 0; t < BM; t++)
            if (red_i[t] == e) Msum += red_p[t];
        g_Ppart[blockIdx.x * E + e] = Pp[0][e] + Pp[1][e] + Pp[2][e] + Pp[3][e];
        g_Mpart[blockIdx.x * E + e] = Msum;
    }
#undef LOAD_REGS
#undef STORE_TILE
#undef COMPUTE
}

// ---- merged finish: reduce partials (per-block, redundant) + aux + capacity fixup ----
__global__ void finish_kernel(float* __restrict__ out, int T, int nblk,
                              int out_size, float cap)
{
    __shared__ float sM[E], sP[E];
    const int tid = threadIdx.x;            // 256
    if (tid < E) {
        float M = 0.f, P = 0.f;
        for (int b = 0; b < nblk; b++) {
            M += g_Mpart[b * E + tid];
            P += g_Ppart[b * E + tid];
        }
        sM[tid] = M; sP[tid] = P;
    }
    __syncthreads();

    if (blockIdx.x == 0 && tid == 0 && out_size > T * E) {
        float accv = 0.f, Tf = (float)T;
        for (int e = 0; e < E; e++) accv += (sM[e] / Tf) * (sP[e] / Tf);
        out[(size_t)T * E] = 0.01f * 64.0f * accv;
    }

    const int t = blockIdx.x * 256 + tid;
    if (t >= T) return;
    const int e = g_topidx[t];
    if (sM[e] <= cap) return;               // fast path: expert under capacity
    // slow path: exact prefix mass (deterministic tie-break on index)
    float p = g_topprob[t];
    float prefix = 0.f;
    for (int t2 = 0; t2 < T; t2++) {
        if (g_topidx[t2] == e) {
            float p2 = g_topprob[t2];
            if (p2 > p || (p2 == p && t2 <= t)) prefix += p2;
        }
    }
    if (prefix > cap) {
#pragma unroll
        for (int j = 0; j < E; j++) out[(size_t)t * E + j] = 0.f;
    }
}

extern "C" void kernel_launch(void* const* d_in, const int* in_sizes, int n_in,
                              void* d_out, int out_size)
{
    const float* x    = (const float*)d_in[0];
    const float* W    = (const float*)d_in[1];
    const float* bias = (const float*)d_in[2];
    float* out = (float*)d_out;

    int T = in_sizes[0] / D;                          // 16384
    int nblk = T / BM;                                // 256
    float cap = (float)(int)((double)T / (double)E);  // 256

    wsplit_kernel<<<D / 16, 256>>>(W);
    router_kernel<<<nblk, NT>>>(x, bias, out, T);
    finish_kernel<<<(T + 255) / 256, 256>>>(out, T, nblk, out_size, cap);
}